// round 9
// baseline (speedup 1.0000x reference)
#include <cuda_runtime.h>
#include <cstdint>

#define IN_CH  512
#define HID    16
#define OUT_CH 64
#define MAX_NODES 100352
#define MAX_EDGES 3276800

// ---- scratch (device globals; no allocation allowed) ----
__device__ float g_deg [MAX_NODES];
__device__ float g_dinv[MAX_NODES];
__device__ float g_h1  [MAX_NODES * HID];   // dinv-prescaled x@W1
__device__ float g_agg1[MAX_NODES * HID];
__device__ float g_agg2[MAX_NODES * HID];

// vectorized f32 reduction (sm_90+): 1 request instead of 4 scalar atomics
__device__ __forceinline__ void red_add_v4(float* p, float4 v) {
    asm volatile("red.global.add.v4.f32 [%0], {%1,%2,%3,%4};"
                 :: "l"(p), "f"(v.x), "f"(v.y), "f"(v.z), "f"(v.w) : "memory");
}

// packed fp32x2 FMA (Blackwell FFMA2 — only reachable via PTX)
__device__ __forceinline__ void ffma2(unsigned long long& d, unsigned long long a,
                                      unsigned long long b) {
    asm("fma.rn.f32x2 %0, %1, %2, %0;" : "+l"(d) : "l"(a), "l"(b));
}

__device__ __forceinline__ void cp_async16(uint32_t dst, const void* src) {
    asm volatile("cp.async.cg.shared.global [%0], [%1], 16;" :: "r"(dst), "l"(src));
}

// ---------------------------------------------------------------- zero (agg1 + deg)
__global__ void zero_kernel(int n) {
    int i = blockIdx.x * blockDim.x + threadIdx.x;
    int t4 = n * HID / 4;
    if (i < t4) ((float4*)g_agg1)[i] = make_float4(0.f, 0.f, 0.f, 0.f);
    if (i < n) g_deg[i] = 0.f;
}

// ---------------------------------------------------------------- degree
__global__ void deg_kernel(const int* __restrict__ ei1, const float* __restrict__ w1, int E1,
                           const int* __restrict__ ei2, const float* __restrict__ w2, int E2) {
    int i = blockIdx.x * blockDim.x + threadIdx.x;
    if (i < E1) {
        atomicAdd(&g_deg[ei1[i]], w1[i]);
    } else {
        int j = i - E1;
        if (j < E2) atomicAdd(&g_deg[ei2[j]], w2[j]);
    }
}

__global__ void dinv_kernel(int n) {
    int i = blockIdx.x * blockDim.x + threadIdx.x;
    if (i >= n) return;
    float d = g_deg[i];
    g_dinv[i] = d > 0.f ? rsqrtf(fmaxf(d, 1e-12f)) : 0.f;
}

// ---------------------------------------------------------------- h1 = dinv .* (x @ W1)
// j-split: 2 lanes per node (each owns 8 of 16 outputs) -> acc = 4 x f32x2 =
// 8 regs -> ~48-56 regs total -> 4 blocks/SM (32 warps). cp.async double
// buffer, KCHUNK=16, smem = 32KB W + 8*2KB tiles = 48KB. Grid-stride over
// 128-node tiles with exactly 148*4 blocks (single wave, no tail).
#define G1_WARPS   8
#define G1_THREADS (G1_WARPS * 32)
#define G1_NPW     16                                  // nodes per warp
#define G1_TILE    (G1_WARPS * G1_NPW)                 // 128 nodes per block-tile
#define G1_KCHUNK  16
#define G1_BUF_FLOATS (G1_NPW * G1_KCHUNK)             // 256 floats per buffer
#define G1_SMEM_FLOATS (IN_CH * HID + G1_WARPS * 2 * G1_BUF_FLOATS)  // 48KB
#define G1_GRID    (148 * 4)

__global__ void __launch_bounds__(G1_THREADS, 4)
gemm1_kernel(const float* __restrict__ x, const float* __restrict__ W1, int n, int ntiles) {
    extern __shared__ float smem[];
    float* Ws = smem;  // [512][16] row-major, 32KB
    const int warp = threadIdx.x >> 5;
    const int lane = threadIdx.x & 31;
    const int sub  = lane & 1;          // j-half: 0 -> cols 0-7, 1 -> cols 8-15
    const int nrow = lane >> 1;         // node-in-warp 0..15
    float* xb = smem + IN_CH * HID + warp * (2 * G1_BUF_FLOATS);
    const uint32_t xb_s = (uint32_t)__cvta_generic_to_shared(xb);

    for (int t = threadIdx.x; t < IN_CH * HID / 4; t += blockDim.x)
        ((float4*)Ws)[t] = ((const float4*)W1)[t];
    __syncthreads();

    const int lswz = (nrow >> 1) & 3;
    // staging coords: 64 float4 per chunk (16 rows x 4 slots), 2 per lane
    const int st_r0 = lane >> 2,     st_c0 = lane & 3;         // rows 0-7
    const int st_r1 = 8 + (lane >> 2), st_c1 = lane & 3;       // rows 8-15
    const uint32_t st_d0 = xb_s + 4u * (st_r0 * G1_KCHUNK + ((st_c0 ^ ((st_r0 >> 1) & 3)) << 2));
    const uint32_t st_d1 = xb_s + 4u * (st_r1 * G1_KCHUNK + ((st_c1 ^ ((st_r1 >> 1) & 3)) << 2));

    for (int tile = blockIdx.x; tile < ntiles; tile += gridDim.x) {
        const int nodebase = tile * G1_TILE + warp * G1_NPW;
        const int node = nodebase + nrow;

        int nd0 = nodebase + st_r0, nd1 = nodebase + st_r1;
        const float4* src0 = (const float4*)x + ((nd0 < n) ? (size_t)nd0 * (IN_CH / 4) : 0) + st_c0;
        const float4* src1 = (const float4*)x + ((nd1 < n) ? (size_t)nd1 * (IN_CH / 4) : 0) + st_c1;

        unsigned long long acc[4];
#pragma unroll
        for (int j = 0; j < 4; j++) acc[j] = 0ull;

        // prefetch chunk 0 into buffer 0
        cp_async16(st_d0, src0);
        cp_async16(st_d1, src1);
        asm volatile("cp.async.commit_group;" ::: "memory");

#pragma unroll 2
        for (int c = 0; c < IN_CH / G1_KCHUNK; c++) {
            const int kc = c * G1_KCHUNK;
            const int cur = c & 1;
            if (c + 1 < IN_CH / G1_KCHUNK) {
                const int nb = (c + 1) & 1;
                const int nk4 = (kc + G1_KCHUNK) >> 2;
                cp_async16(st_d0 + 4u * nb * G1_BUF_FLOATS, src0 + nk4);
                cp_async16(st_d1 + 4u * nb * G1_BUF_FLOATS, src1 + nk4);
                asm volatile("cp.async.commit_group;" ::: "memory");
                asm volatile("cp.async.wait_group 1;" ::: "memory");
            } else {
                asm volatile("cp.async.wait_group 0;" ::: "memory");
            }
            __syncwarp();

            const float* xrow = xb + cur * G1_BUF_FLOATS + nrow * G1_KCHUNK;
#pragma unroll
            for (int k4 = 0; k4 < 4; k4++) {
                const float4 xq = *(const float4*)(xrow + ((k4 ^ lswz) << 2));
                const float xv4[4] = {xq.x, xq.y, xq.z, xq.w};
#pragma unroll
                for (int s = 0; s < 4; s++) {
                    unsigned long long xx;
                    asm("mov.b64 %0, {%1, %1};" : "=l"(xx) : "f"(xv4[s]));
                    const ulonglong2* wr =
                        (const ulonglong2*)(Ws + (kc + k4 * 4 + s) * HID + sub * 8);
                    ulonglong2 w0 = wr[0], w1 = wr[1];
                    ffma2(acc[0], w0.x, xx); ffma2(acc[1], w0.y, xx);
                    ffma2(acc[2], w1.x, xx); ffma2(acc[3], w1.y, xx);
                }
            }
            __syncwarp();
        }

        if (node < n) {
            float dv = __ldg(g_dinv + node);
            float out[8];
#pragma unroll
            for (int j = 0; j < 4; j++)
                asm("mov.b64 {%0, %1}, %2;" : "=f"(out[2*j]), "=f"(out[2*j+1]) : "l"(acc[j]));
#pragma unroll
            for (int j = 0; j < 8; j++) out[j] *= dv;
            float4* o = (float4*)(g_h1 + (size_t)node * HID + sub * 8);
            o[0] = make_float4(out[0], out[1], out[2], out[3]);
            o[1] = make_float4(out[4], out[5], out[6], out[7]);
        }
    }
}

// ---------------------------------------------------------------- scatter
// quad-per-edge fp32 (REDG-throughput floor): 4 lanes per edge, float4 each.
template <int LAYER>
__global__ void scatter_kernel(const int* __restrict__ ei1, const float* __restrict__ w1, int E1,
                               const int* __restrict__ ei2, const float* __restrict__ w2, int E2) {
    int t = blockIdx.x * blockDim.x + threadIdx.x;
    int e   = t >> 2;
    int sub = t & 3;
    int row, col;
    float w;
    if (e < E1) {
        row = __ldg(ei1 + e); col = __ldg(ei1 + E1 + e); w = __ldg(w1 + e);
    } else {
        int j = e - E1;
        if (j >= E2) return;
        row = __ldg(ei2 + j); col = __ldg(ei2 + E2 + j); w = __ldg(w2 + j);
    }

    const float* src = (LAYER == 1) ? g_h1 : g_agg1;
    float*       dst = (LAYER == 1) ? g_agg1 : g_agg2;

    float4 v = __ldg(((const float4*)(src + (size_t)col * HID)) + sub);
    v.x *= w; v.y *= w; v.z *= w; v.w *= w;
    red_add_v4(dst + (size_t)row * HID + sub * 4, v);
}

// ---------------------------------------------------------------- agg1 = dinv.*relu(dinv.*agg1 + b1); zero agg2
__global__ void relu_kernel(const float* __restrict__ b1, int n) {
    int i = blockIdx.x * blockDim.x + threadIdx.x;   // float4 index
    int t4 = n * HID / 4;
    if (i >= t4) return;
    int node = i >> 2;
    float dv = __ldg(g_dinv + node);
    float4 b = __ldg(((const float4*)b1) + (i & 3));
    float4 v = ((float4*)g_agg1)[i];
    v.x = dv * fmaxf(dv * v.x + b.x, 0.f);
    v.y = dv * fmaxf(dv * v.y + b.y, 0.f);
    v.z = dv * fmaxf(dv * v.z + b.z, 0.f);
    v.w = dv * fmaxf(dv * v.w + b.w, 0.f);
    ((float4*)g_agg1)[i] = v;
    ((float4*)g_agg2)[i] = make_float4(0.f, 0.f, 0.f, 0.f);
}

// ---------------------------------------------------------------- out = log_softmax((dinv.*agg2) @ W2 + b2)
#define OUT_WARPS 8
__global__ void out_kernel(const float* __restrict__ W2, const float* __restrict__ b2,
                           float* __restrict__ out, int n) {
    __shared__ float W2s[HID * OUT_CH];
    for (int t = threadIdx.x; t < HID * OUT_CH / 4; t += blockDim.x)
        ((float4*)W2s)[t] = ((const float4*)W2)[t];
    __syncthreads();

    int warp = threadIdx.x >> 5, lane = threadIdx.x & 31;
    int node = blockIdx.x * OUT_WARPS + warp;
    if (node >= n) return;

    float dv = __ldg(g_dinv + node);
    const float4* a4 = (const float4*)(g_agg2 + (size_t)node * HID);
    float4 a0 = a4[0], a1 = a4[1], a2 = a4[2], a3 = a4[3];
    float a[16];
    a[0]  = a0.x; a[1]  = a0.y; a[2]  = a0.z; a[3]  = a0.w;
    a[4]  = a1.x; a[5]  = a1.y; a[6]  = a1.z; a[7]  = a1.w;
    a[8]  = a2.x; a[9]  = a2.y; a[10] = a2.z; a[11] = a2.w;
    a[12] = a3.x; a[13] = a3.y; a[14] = a3.z; a[15] = a3.w;
#pragma unroll
    for (int k = 0; k < HID; k++) a[k] *= dv;

    float acc0 = b2[lane];
    float acc1 = b2[lane + 32];
#pragma unroll
    for (int k = 0; k < HID; k++) {
        acc0 += a[k] * W2s[k * OUT_CH + lane];
        acc1 += a[k] * W2s[k * OUT_CH + lane + 32];
    }

    float m = fmaxf(acc0, acc1);
#pragma unroll
    for (int off = 16; off >= 1; off >>= 1)
        m = fmaxf(m, __shfl_xor_sync(0xffffffffu, m, off));
    float s = expf(acc0 - m) + expf(acc1 - m);
#pragma unroll
    for (int off = 16; off >= 1; off >>= 1)
        s += __shfl_xor_sync(0xffffffffu, s, off);
    float lse = m + logf(s);

    out[(size_t)node * OUT_CH + lane]      = acc0 - lse;
    out[(size_t)node * OUT_CH + lane + 32] = acc1 - lse;
}

// ---------------------------------------------------------------- launch
extern "C" void kernel_launch(void* const* d_in, const int* in_sizes, int n_in,
                              void* d_out, int out_size) {
    const float* x   = (const float*)d_in[0];
    const int*   ei1 = (const int*)  d_in[1];
    const float* ew1 = (const float*)d_in[2];
    const int*   ei2 = (const int*)  d_in[3];
    const float* ew2 = (const float*)d_in[4];
    const float* W1  = (const float*)d_in[5];
    const float* b1  = (const float*)d_in[6];
    const float* W2  = (const float*)d_in[7];
    const float* b2  = (const float*)d_in[8];
    float* out = (float*)d_out;

    int n  = in_sizes[0] / IN_CH;
    int E1 = in_sizes[2];
    int E2 = in_sizes[4];
    int Et = E1 + E2;
    int ntiles = (n + G1_TILE - 1) / G1_TILE;
    int g1grid = ntiles < G1_GRID ? ntiles : G1_GRID;

    const int G1_SMEM = G1_SMEM_FLOATS * (int)sizeof(float);
    cudaFuncSetAttribute(gemm1_kernel, cudaFuncAttributeMaxDynamicSharedMemorySize, G1_SMEM);

    zero_kernel<<<(n * HID / 4 + 255) / 256, 256>>>(n);
    deg_kernel<<<(Et + 255) / 256, 256>>>(ei1, ew1, E1, ei2, ew2, E2);
    dinv_kernel<<<(n + 255) / 256, 256>>>(n);
    gemm1_kernel<<<g1grid, G1_THREADS, G1_SMEM>>>(x, W1, n, ntiles);
    scatter_kernel<1><<<(4 * Et + 255) / 256, 256>>>(ei1, ew1, E1, ei2, ew2, E2);
    relu_kernel<<<(n * HID / 4 + 255) / 256, 256>>>(b1, n);
    scatter_kernel<2><<<(4 * Et + 255) / 256, 256>>>(ei1, ew1, E1, ei2, ew2, E2);
    out_kernel<<<(n + OUT_WARPS - 1) / OUT_WARPS, OUT_WARPS * 32>>>(W2, b2, out, n);
}

// round 10
// speedup vs baseline: 1.0027x; 1.0027x over previous
#include <cuda_runtime.h>
#include <cstdint>

#define IN_CH  512
#define HID    16
#define OUT_CH 64
#define MAX_NODES 100352
#define MAX_EDGES 3276800

// ---- scratch (device globals; no allocation allowed) ----
__device__ float g_deg [MAX_NODES];
__device__ float g_dinv[MAX_NODES];
__device__ float g_h1  [MAX_NODES * HID];   // dinv-prescaled x@W1
__device__ float g_agg1[MAX_NODES * HID];
__device__ float g_agg2[MAX_NODES * HID];

// vectorized f32 reduction (sm_90+): 1 request instead of 4 scalar atomics
__device__ __forceinline__ void red_add_v4(float* p, float4 v) {
    asm volatile("red.global.add.v4.f32 [%0], {%1,%2,%3,%4};"
                 :: "l"(p), "f"(v.x), "f"(v.y), "f"(v.z), "f"(v.w) : "memory");
}

// packed fp32x2 FMA (Blackwell FFMA2 — only reachable via PTX)
__device__ __forceinline__ void ffma2(unsigned long long& d, unsigned long long a,
                                      unsigned long long b) {
    asm("fma.rn.f32x2 %0, %1, %2, %0;" : "+l"(d) : "l"(a), "l"(b));
}

__device__ __forceinline__ void cp_async16(uint32_t dst, const void* src) {
    asm volatile("cp.async.cg.shared.global [%0], [%1], 16;" :: "r"(dst), "l"(src));
}

// ---------------------------------------------------------------- zero (agg1 + deg)
__global__ void zero_kernel(int n) {
    int i = blockIdx.x * blockDim.x + threadIdx.x;
    int t4 = n * HID / 4;
    if (i < t4) ((float4*)g_agg1)[i] = make_float4(0.f, 0.f, 0.f, 0.f);
    if (i < n) g_deg[i] = 0.f;
}

// ---------------------------------------------------------------- degree
__global__ void deg_kernel(const int* __restrict__ ei1, const float* __restrict__ w1, int E1,
                           const int* __restrict__ ei2, const float* __restrict__ w2, int E2) {
    int i = blockIdx.x * blockDim.x + threadIdx.x;
    if (i < E1) {
        atomicAdd(&g_deg[ei1[i]], w1[i]);
    } else {
        int j = i - E1;
        if (j < E2) atomicAdd(&g_deg[ei2[j]], w2[j]);
    }
}

__global__ void dinv_kernel(int n) {
    int i = blockIdx.x * blockDim.x + threadIdx.x;
    if (i >= n) return;
    float d = g_deg[i];
    g_dinv[i] = d > 0.f ? rsqrtf(fmaxf(d, 1e-12f)) : 0.f;
}

// ---------------------------------------------------------------- h1 = dinv .* (x @ W1)
// j-split: 2 lanes per node (each owns 8 of 16 outputs) -> acc = 4 x f32x2 =
// 8 regs -> ~48-56 regs total -> 4 blocks/SM (32 warps). cp.async double
// buffer, KCHUNK=16, smem = 32KB W + 8*2KB tiles = 48KB. Grid-stride over
// 128-node tiles with exactly 148*4 blocks (single wave, no tail).
#define G1_WARPS   8
#define G1_THREADS (G1_WARPS * 32)
#define G1_NPW     16                                  // nodes per warp
#define G1_TILE    (G1_WARPS * G1_NPW)                 // 128 nodes per block-tile
#define G1_KCHUNK  16
#define G1_BUF_FLOATS (G1_NPW * G1_KCHUNK)             // 256 floats per buffer
#define G1_SMEM_FLOATS (IN_CH * HID + G1_WARPS * 2 * G1_BUF_FLOATS)  // 48KB
#define G1_GRID    (148 * 4)

__global__ void __launch_bounds__(G1_THREADS, 4)
gemm1_kernel(const float* __restrict__ x, const float* __restrict__ W1, int n, int ntiles) {
    extern __shared__ float smem[];
    float* Ws = smem;  // [512][16] row-major, 32KB
    const int warp = threadIdx.x >> 5;
    const int lane = threadIdx.x & 31;
    const int sub  = lane & 1;          // j-half: 0 -> cols 0-7, 1 -> cols 8-15
    const int nrow = lane >> 1;         // node-in-warp 0..15
    float* xb = smem + IN_CH * HID + warp * (2 * G1_BUF_FLOATS);
    const uint32_t xb_s = (uint32_t)__cvta_generic_to_shared(xb);

    for (int t = threadIdx.x; t < IN_CH * HID / 4; t += blockDim.x)
        ((float4*)Ws)[t] = ((const float4*)W1)[t];
    __syncthreads();

    const int lswz = (nrow >> 1) & 3;
    // staging coords: 64 float4 per chunk (16 rows x 4 slots), 2 per lane
    const int st_r0 = lane >> 2,     st_c0 = lane & 3;         // rows 0-7
    const int st_r1 = 8 + (lane >> 2), st_c1 = lane & 3;       // rows 8-15
    const uint32_t st_d0 = xb_s + 4u * (st_r0 * G1_KCHUNK + ((st_c0 ^ ((st_r0 >> 1) & 3)) << 2));
    const uint32_t st_d1 = xb_s + 4u * (st_r1 * G1_KCHUNK + ((st_c1 ^ ((st_r1 >> 1) & 3)) << 2));

    for (int tile = blockIdx.x; tile < ntiles; tile += gridDim.x) {
        const int nodebase = tile * G1_TILE + warp * G1_NPW;
        const int node = nodebase + nrow;

        int nd0 = nodebase + st_r0, nd1 = nodebase + st_r1;
        const float4* src0 = (const float4*)x + ((nd0 < n) ? (size_t)nd0 * (IN_CH / 4) : 0) + st_c0;
        const float4* src1 = (const float4*)x + ((nd1 < n) ? (size_t)nd1 * (IN_CH / 4) : 0) + st_c1;

        unsigned long long acc[4];
#pragma unroll
        for (int j = 0; j < 4; j++) acc[j] = 0ull;

        // prefetch chunk 0 into buffer 0
        cp_async16(st_d0, src0);
        cp_async16(st_d1, src1);
        asm volatile("cp.async.commit_group;" ::: "memory");

#pragma unroll 2
        for (int c = 0; c < IN_CH / G1_KCHUNK; c++) {
            const int kc = c * G1_KCHUNK;
            const int cur = c & 1;
            if (c + 1 < IN_CH / G1_KCHUNK) {
                const int nb = (c + 1) & 1;
                const int nk4 = (kc + G1_KCHUNK) >> 2;
                cp_async16(st_d0 + 4u * nb * G1_BUF_FLOATS, src0 + nk4);
                cp_async16(st_d1 + 4u * nb * G1_BUF_FLOATS, src1 + nk4);
                asm volatile("cp.async.commit_group;" ::: "memory");
                asm volatile("cp.async.wait_group 1;" ::: "memory");
            } else {
                asm volatile("cp.async.wait_group 0;" ::: "memory");
            }
            __syncwarp();

            const float* xrow = xb + cur * G1_BUF_FLOATS + nrow * G1_KCHUNK;
#pragma unroll
            for (int k4 = 0; k4 < 4; k4++) {
                const float4 xq = *(const float4*)(xrow + ((k4 ^ lswz) << 2));
                const float xv4[4] = {xq.x, xq.y, xq.z, xq.w};
#pragma unroll
                for (int s = 0; s < 4; s++) {
                    unsigned long long xx;
                    asm("mov.b64 %0, {%1, %1};" : "=l"(xx) : "f"(xv4[s]));
                    const ulonglong2* wr =
                        (const ulonglong2*)(Ws + (kc + k4 * 4 + s) * HID + sub * 8);
                    ulonglong2 w0 = wr[0], w1 = wr[1];
                    ffma2(acc[0], w0.x, xx); ffma2(acc[1], w0.y, xx);
                    ffma2(acc[2], w1.x, xx); ffma2(acc[3], w1.y, xx);
                }
            }
            __syncwarp();
        }

        if (node < n) {
            float dv = __ldg(g_dinv + node);
            float out[8];
#pragma unroll
            for (int j = 0; j < 4; j++)
                asm("mov.b64 {%0, %1}, %2;" : "=f"(out[2*j]), "=f"(out[2*j+1]) : "l"(acc[j]));
#pragma unroll
            for (int j = 0; j < 8; j++) out[j] *= dv;
            float4* o = (float4*)(g_h1 + (size_t)node * HID + sub * 8);
            o[0] = make_float4(out[0], out[1], out[2], out[3]);
            o[1] = make_float4(out[4], out[5], out[6], out[7]);
        }
    }
}

// ---------------------------------------------------------------- scatter
// quad-per-edge fp32 (REDG-throughput floor): 4 lanes per edge, float4 each.
template <int LAYER>
__global__ void scatter_kernel(const int* __restrict__ ei1, const float* __restrict__ w1, int E1,
                               const int* __restrict__ ei2, const float* __restrict__ w2, int E2) {
    int t = blockIdx.x * blockDim.x + threadIdx.x;
    int e   = t >> 2;
    int sub = t & 3;
    int row, col;
    float w;
    if (e < E1) {
        row = __ldg(ei1 + e); col = __ldg(ei1 + E1 + e); w = __ldg(w1 + e);
    } else {
        int j = e - E1;
        if (j >= E2) return;
        row = __ldg(ei2 + j); col = __ldg(ei2 + E2 + j); w = __ldg(w2 + j);
    }

    const float* src = (LAYER == 1) ? g_h1 : g_agg1;
    float*       dst = (LAYER == 1) ? g_agg1 : g_agg2;

    float4 v = __ldg(((const float4*)(src + (size_t)col * HID)) + sub);
    v.x *= w; v.y *= w; v.z *= w; v.w *= w;
    red_add_v4(dst + (size_t)row * HID + sub * 4, v);
}

// ---------------------------------------------------------------- agg1 = dinv.*relu(dinv.*agg1 + b1); zero agg2
__global__ void relu_kernel(const float* __restrict__ b1, int n) {
    int i = blockIdx.x * blockDim.x + threadIdx.x;   // float4 index
    int t4 = n * HID / 4;
    if (i >= t4) return;
    int node = i >> 2;
    float dv = __ldg(g_dinv + node);
    float4 b = __ldg(((const float4*)b1) + (i & 3));
    float4 v = ((float4*)g_agg1)[i];
    v.x = dv * fmaxf(dv * v.x + b.x, 0.f);
    v.y = dv * fmaxf(dv * v.y + b.y, 0.f);
    v.z = dv * fmaxf(dv * v.z + b.z, 0.f);
    v.w = dv * fmaxf(dv * v.w + b.w, 0.f);
    ((float4*)g_agg1)[i] = v;
    ((float4*)g_agg2)[i] = make_float4(0.f, 0.f, 0.f, 0.f);
}

// ---------------------------------------------------------------- out = log_softmax((dinv.*agg2) @ W2 + b2)
#define OUT_WARPS 8
__global__ void out_kernel(const float* __restrict__ W2, const float* __restrict__ b2,
                           float* __restrict__ out, int n) {
    __shared__ float W2s[HID * OUT_CH];
    for (int t = threadIdx.x; t < HID * OUT_CH / 4; t += blockDim.x)
        ((float4*)W2s)[t] = ((const float4*)W2)[t];
    __syncthreads();

    int warp = threadIdx.x >> 5, lane = threadIdx.x & 31;
    int node = blockIdx.x * OUT_WARPS + warp;
    if (node >= n) return;

    float dv = __ldg(g_dinv + node);
    const float4* a4 = (const float4*)(g_agg2 + (size_t)node * HID);
    float4 a0 = a4[0], a1 = a4[1], a2 = a4[2], a3 = a4[3];
    float a[16];
    a[0]  = a0.x; a[1]  = a0.y; a[2]  = a0.z; a[3]  = a0.w;
    a[4]  = a1.x; a[5]  = a1.y; a[6]  = a1.z; a[7]  = a1.w;
    a[8]  = a2.x; a[9]  = a2.y; a[10] = a2.z; a[11] = a2.w;
    a[12] = a3.x; a[13] = a3.y; a[14] = a3.z; a[15] = a3.w;
#pragma unroll
    for (int k = 0; k < HID; k++) a[k] *= dv;

    float acc0 = b2[lane];
    float acc1 = b2[lane + 32];
#pragma unroll
    for (int k = 0; k < HID; k++) {
        acc0 += a[k] * W2s[k * OUT_CH + lane];
        acc1 += a[k] * W2s[k * OUT_CH + lane + 32];
    }

    float m = fmaxf(acc0, acc1);
#pragma unroll
    for (int off = 16; off >= 1; off >>= 1)
        m = fmaxf(m, __shfl_xor_sync(0xffffffffu, m, off));
    float s = expf(acc0 - m) + expf(acc1 - m);
#pragma unroll
    for (int off = 16; off >= 1; off >>= 1)
        s += __shfl_xor_sync(0xffffffffu, s, off);
    float lse = m + logf(s);

    out[(size_t)node * OUT_CH + lane]      = acc0 - lse;
    out[(size_t)node * OUT_CH + lane + 32] = acc1 - lse;
}

// ---------------------------------------------------------------- launch
extern "C" void kernel_launch(void* const* d_in, const int* in_sizes, int n_in,
                              void* d_out, int out_size) {
    const float* x   = (const float*)d_in[0];
    const int*   ei1 = (const int*)  d_in[1];
    const float* ew1 = (const float*)d_in[2];
    const int*   ei2 = (const int*)  d_in[3];
    const float* ew2 = (const float*)d_in[4];
    const float* W1  = (const float*)d_in[5];
    const float* b1  = (const float*)d_in[6];
    const float* W2  = (const float*)d_in[7];
    const float* b2  = (const float*)d_in[8];
    float* out = (float*)d_out;

    int n  = in_sizes[0] / IN_CH;
    int E1 = in_sizes[2];
    int E2 = in_sizes[4];
    int Et = E1 + E2;
    int ntiles = (n + G1_TILE - 1) / G1_TILE;
    int g1grid = ntiles < G1_GRID ? ntiles : G1_GRID;

    const int G1_SMEM = G1_SMEM_FLOATS * (int)sizeof(float);
    cudaFuncSetAttribute(gemm1_kernel, cudaFuncAttributeMaxDynamicSharedMemorySize, G1_SMEM);

    zero_kernel<<<(n * HID / 4 + 255) / 256, 256>>>(n);
    deg_kernel<<<(Et + 255) / 256, 256>>>(ei1, ew1, E1, ei2, ew2, E2);
    dinv_kernel<<<(n + 255) / 256, 256>>>(n);
    gemm1_kernel<<<g1grid, G1_THREADS, G1_SMEM>>>(x, W1, n, ntiles);
    scatter_kernel<1><<<(4 * Et + 255) / 256, 256>>>(ei1, ew1, E1, ei2, ew2, E2);
    relu_kernel<<<(n * HID / 4 + 255) / 256, 256>>>(b1, n);
    scatter_kernel<2><<<(4 * Et + 255) / 256, 256>>>(ei1, ew1, E1, ei2, ew2, E2);
    out_kernel<<<(n + OUT_WARPS - 1) / OUT_WARPS, OUT_WARPS * 32>>>(W2, b2, out, n);
}

// round 11
// speedup vs baseline: 1.1710x; 1.1678x over previous
#include <cuda_runtime.h>
#include <cuda_fp16.h>
#include <cstdint>

#define IN_CH  512
#define HID    16
#define OUT_CH 64
#define MAX_NODES 100352
#define MAX_EDGES 3276800

// ---- scratch (device globals; no allocation allowed) ----
__device__ float  g_deg  [MAX_NODES];
__device__ float  g_dinv [MAX_NODES];
__device__ __half g_h1h  [MAX_NODES * HID];  // fp16 dinv-prescaled x@W1 (3.2MB, L2-resident)
__device__ __half g_zh   [MAX_NODES * HID];  // fp16 dinv*relu(dinv*agg1+b1)
__device__ __half g_agg1h[MAX_NODES * HID];  // fp16 accumulation buffers
__device__ __half g_agg2h[MAX_NODES * HID];

// 128-bit fp16x2 reduction: 8 halves in ONE red-lane-op (the scatter currency)
__device__ __forceinline__ void red_add_v4h2(__half* p, uint32_t r0, uint32_t r1,
                                             uint32_t r2, uint32_t r3) {
    asm volatile("red.global.add.noftz.v4.f16x2 [%0], {%1,%2,%3,%4};"
                 :: "l"(p), "r"(r0), "r"(r1), "r"(r2), "r"(r3) : "memory");
}

// packed fp32x2 FMA (Blackwell FFMA2 — only reachable via PTX)
__device__ __forceinline__ void ffma2(unsigned long long& d, unsigned long long a,
                                      unsigned long long b) {
    asm("fma.rn.f32x2 %0, %1, %2, %0;" : "+l"(d) : "l"(a), "l"(b));
}

__device__ __forceinline__ void cp_async16(uint32_t dst, const void* src) {
    asm volatile("cp.async.cg.shared.global [%0], [%1], 16;" :: "r"(dst), "l"(src));
}

// ---------------------------------------------------------------- zero (agg1h + deg)
__global__ void zero_kernel(int n) {
    int i = blockIdx.x * blockDim.x + threadIdx.x;
    int t4 = n * HID / 8;            // uint4 = 8 halves
    if (i < t4) ((uint4*)g_agg1h)[i] = make_uint4(0u, 0u, 0u, 0u);
    if (i < n) g_deg[i] = 0.f;
}

// ---------------------------------------------------------------- degree
__global__ void deg_kernel(const int* __restrict__ ei1, const float* __restrict__ w1, int E1,
                           const int* __restrict__ ei2, const float* __restrict__ w2, int E2) {
    int i = blockIdx.x * blockDim.x + threadIdx.x;
    if (i < E1) {
        atomicAdd(&g_deg[ei1[i]], w1[i]);
    } else {
        int j = i - E1;
        if (j < E2) atomicAdd(&g_deg[ei2[j]], w2[j]);
    }
}

__global__ void dinv_kernel(int n) {
    int i = blockIdx.x * blockDim.x + threadIdx.x;
    if (i >= n) return;
    float d = g_deg[i];
    g_dinv[i] = d > 0.f ? rsqrtf(fmaxf(d, 1e-12f)) : 0.f;
}

// ---------------------------------------------------------------- h1h = fp16(dinv .* (x @ W1))
// R8 champion shape: lane-per-node, KCHUNK=16 XOR-swizzled tile, cp.async
// double buffer. fp16 output epilogue only change.
#define G1_WARPS   8
#define G1_THREADS (G1_WARPS * 32)
#define G1_KCHUNK  16
#define G1_BUF_FLOATS (32 * G1_KCHUNK)                 // 512 floats per buffer
#define G1_SMEM_FLOATS (IN_CH * HID + G1_WARPS * 2 * G1_BUF_FLOATS)  // 64KB

__global__ void __launch_bounds__(G1_THREADS, 3)
gemm1_kernel(const float* __restrict__ x, const float* __restrict__ W1, int n) {
    extern __shared__ float smem[];
    float* Ws = smem;  // [512][16] row-major, 32KB
    const int warp = threadIdx.x >> 5;
    const int lane = threadIdx.x & 31;
    float* xb = smem + IN_CH * HID + warp * (2 * G1_BUF_FLOATS);
    const uint32_t xb_s = (uint32_t)__cvta_generic_to_shared(xb);

    for (int t = threadIdx.x; t < IN_CH * HID / 4; t += blockDim.x)
        ((float4*)Ws)[t] = ((const float4*)W1)[t];
    __syncthreads();

    const int nodebase = blockIdx.x * G1_THREADS + warp * 32;
    const int node = nodebase + lane;
    const int lswz = (lane >> 1) & 3;

    int st_r[4], st_c[4];
    const float4* st_src[4];
#pragma unroll
    for (int t = 0; t < 4; t++) {
        int idx = t * 32 + lane;
        st_r[t] = idx >> 2;
        st_c[t] = idx & 3;
        int nd = nodebase + st_r[t];
        st_src[t] = (const float4*)x + ((nd < n) ? (size_t)nd * (IN_CH / 4) : 0) + st_c[t];
    }

    unsigned long long acc[8];
#pragma unroll
    for (int j = 0; j < 8; j++) acc[j] = 0ull;

#pragma unroll
    for (int t = 0; t < 4; t++) {
        uint32_t dst = xb_s + 4u * (st_r[t] * G1_KCHUNK +
                                    ((st_c[t] ^ ((st_r[t] >> 1) & 3)) << 2));
        cp_async16(dst, st_src[t]);
    }
    asm volatile("cp.async.commit_group;" ::: "memory");

#pragma unroll 2
    for (int c = 0; c < IN_CH / G1_KCHUNK; c++) {
        const int kc = c * G1_KCHUNK;
        const int cur = c & 1;
        if (c + 1 < IN_CH / G1_KCHUNK) {
            const int nb = (c + 1) & 1;
            const int nk4 = (kc + G1_KCHUNK) >> 2;
#pragma unroll
            for (int t = 0; t < 4; t++) {
                uint32_t dst = xb_s + 4u * (nb * G1_BUF_FLOATS + st_r[t] * G1_KCHUNK +
                                            ((st_c[t] ^ ((st_r[t] >> 1) & 3)) << 2));
                cp_async16(dst, st_src[t] + nk4);
            }
            asm volatile("cp.async.commit_group;" ::: "memory");
            asm volatile("cp.async.wait_group 1;" ::: "memory");
        } else {
            asm volatile("cp.async.wait_group 0;" ::: "memory");
        }
        __syncwarp();

        const float* xrow = xb + cur * G1_BUF_FLOATS + lane * G1_KCHUNK;
#pragma unroll
        for (int k4 = 0; k4 < 4; k4++) {
            const float4 xq = *(const float4*)(xrow + ((k4 ^ lswz) << 2));
            const float xv4[4] = {xq.x, xq.y, xq.z, xq.w};
#pragma unroll
            for (int s = 0; s < 4; s++) {
                unsigned long long xx;
                asm("mov.b64 %0, {%1, %1};" : "=l"(xx) : "f"(xv4[s]));
                const ulonglong2* wr = (const ulonglong2*)(Ws + (kc + k4 * 4 + s) * HID);
                ulonglong2 w0 = wr[0], w1 = wr[1], w2 = wr[2], w3 = wr[3];
                ffma2(acc[0], w0.x, xx); ffma2(acc[1], w0.y, xx);
                ffma2(acc[2], w1.x, xx); ffma2(acc[3], w1.y, xx);
                ffma2(acc[4], w2.x, xx); ffma2(acc[5], w2.y, xx);
                ffma2(acc[6], w3.x, xx); ffma2(acc[7], w3.y, xx);
            }
        }
        __syncwarp();
    }

    if (node < n) {
        float dv = __ldg(g_dinv + node);
        float out[HID];
#pragma unroll
        for (int j = 0; j < 8; j++)
            asm("mov.b64 {%0, %1}, %2;" : "=f"(out[2*j]), "=f"(out[2*j+1]) : "l"(acc[j]));
        unsigned hu[8];
#pragma unroll
        for (int j = 0; j < 8; j++) {
            __half2 h = __floats2half2_rn(out[2*j] * dv, out[2*j+1] * dv);
            hu[j] = *(unsigned*)&h;
        }
        uint4* o = (uint4*)(g_h1h + (size_t)node * HID);
        o[0] = make_uint4(hu[0], hu[1], hu[2], hu[3]);
        o[1] = make_uint4(hu[4], hu[5], hu[6], hu[7]);
    }
}

// ---------------------------------------------------------------- scatter (fp16 reds)
// 2 lanes per edge, each: gather 16B (8 halves), scale by w (half2), ONE
// red.v4.f16x2 (8 halves, 128-bit) -> 6.4M red-lane-ops vs 12.8M for fp32.
template <int LAYER>
__global__ void scatter_kernel(const int* __restrict__ ei1, const float* __restrict__ w1, int E1,
                               const int* __restrict__ ei2, const float* __restrict__ w2, int E2) {
    int t = blockIdx.x * blockDim.x + threadIdx.x;
    int e   = t >> 1;
    int sub = t & 1;
    int row, col;
    float w;
    if (e < E1) {
        row = __ldg(ei1 + e); col = __ldg(ei1 + E1 + e); w = __ldg(w1 + e);
    } else {
        int j = e - E1;
        if (j >= E2) return;
        row = __ldg(ei2 + j); col = __ldg(ei2 + E2 + j); w = __ldg(w2 + j);
    }

    const __half* src = (LAYER == 1) ? g_h1h : g_zh;
    __half*       dst = (LAYER == 1) ? g_agg1h : g_agg2h;

    uint4 hv = __ldg((const uint4*)(src + (size_t)col * HID + sub * 8));
    __half2 w2h = __float2half2_rn(w);
    __half2 h0 = __hmul2(*(__half2*)&hv.x, w2h);
    __half2 h1 = __hmul2(*(__half2*)&hv.y, w2h);
    __half2 h2 = __hmul2(*(__half2*)&hv.z, w2h);
    __half2 h3 = __hmul2(*(__half2*)&hv.w, w2h);

    red_add_v4h2(dst + (size_t)row * HID + sub * 8,
                 *(uint32_t*)&h0, *(uint32_t*)&h1, *(uint32_t*)&h2, *(uint32_t*)&h3);
}

// ---------------------------------------------------------------- zh = fp16(dinv.*relu(dinv.*agg1h + b1)); zero agg2h
// one thread per half-node (8 halves)
__global__ void relu_kernel(const float* __restrict__ b1, int n) {
    int i = blockIdx.x * blockDim.x + threadIdx.x;
    if (i >= 2 * n) return;
    int node = i >> 1, sub = i & 1;
    float dv = __ldg(g_dinv + node);
    uint4 u = ((const uint4*)(g_agg1h))[i];
    const float4* bb = (const float4*)(b1 + sub * 8);
    float4 b0 = __ldg(bb), b1v = __ldg(bb + 1);
    float2 f0 = __half22float2(*(__half2*)&u.x);
    float2 f1 = __half22float2(*(__half2*)&u.y);
    float2 f2 = __half22float2(*(__half2*)&u.z);
    float2 f3 = __half22float2(*(__half2*)&u.w);
    f0.x = dv * fmaxf(dv * f0.x + b0.x, 0.f);  f0.y = dv * fmaxf(dv * f0.y + b0.y, 0.f);
    f1.x = dv * fmaxf(dv * f1.x + b0.z, 0.f);  f1.y = dv * fmaxf(dv * f1.y + b0.w, 0.f);
    f2.x = dv * fmaxf(dv * f2.x + b1v.x, 0.f); f2.y = dv * fmaxf(dv * f2.y + b1v.y, 0.f);
    f3.x = dv * fmaxf(dv * f3.x + b1v.z, 0.f); f3.y = dv * fmaxf(dv * f3.y + b1v.w, 0.f);
    __half2 h0 = __floats2half2_rn(f0.x, f0.y);
    __half2 h1 = __floats2half2_rn(f1.x, f1.y);
    __half2 h2 = __floats2half2_rn(f2.x, f2.y);
    __half2 h3 = __floats2half2_rn(f3.x, f3.y);
    ((uint4*)g_zh)[i] = make_uint4(*(unsigned*)&h0, *(unsigned*)&h1,
                                   *(unsigned*)&h2, *(unsigned*)&h3);
    ((uint4*)g_agg2h)[i] = make_uint4(0u, 0u, 0u, 0u);
}

// ---------------------------------------------------------------- out = log_softmax((dinv.*agg2h) @ W2 + b2)
#define OUT_WARPS 8
__global__ void out_kernel(const float* __restrict__ W2, const float* __restrict__ b2,
                           float* __restrict__ out, int n) {
    __shared__ float W2s[HID * OUT_CH];
    for (int t = threadIdx.x; t < HID * OUT_CH / 4; t += blockDim.x)
        ((float4*)W2s)[t] = ((const float4*)W2)[t];
    __syncthreads();

    int warp = threadIdx.x >> 5, lane = threadIdx.x & 31;
    int node = blockIdx.x * OUT_WARPS + warp;
    if (node >= n) return;

    float dv = __ldg(g_dinv + node);
    const uint4* a4 = (const uint4*)(g_agg2h + (size_t)node * HID);
    uint4 u0 = __ldg(a4), u1 = __ldg(a4 + 1);
    float a[16];
    {
        float2 f;
        f = __half22float2(*(__half2*)&u0.x); a[0]  = f.x; a[1]  = f.y;
        f = __half22float2(*(__half2*)&u0.y); a[2]  = f.x; a[3]  = f.y;
        f = __half22float2(*(__half2*)&u0.z); a[4]  = f.x; a[5]  = f.y;
        f = __half22float2(*(__half2*)&u0.w); a[6]  = f.x; a[7]  = f.y;
        f = __half22float2(*(__half2*)&u1.x); a[8]  = f.x; a[9]  = f.y;
        f = __half22float2(*(__half2*)&u1.y); a[10] = f.x; a[11] = f.y;
        f = __half22float2(*(__half2*)&u1.z); a[12] = f.x; a[13] = f.y;
        f = __half22float2(*(__half2*)&u1.w); a[14] = f.x; a[15] = f.y;
    }
#pragma unroll
    for (int k = 0; k < HID; k++) a[k] *= dv;

    float acc0 = b2[lane];
    float acc1 = b2[lane + 32];
#pragma unroll
    for (int k = 0; k < HID; k++) {
        acc0 += a[k] * W2s[k * OUT_CH + lane];
        acc1 += a[k] * W2s[k * OUT_CH + lane + 32];
    }

    float m = fmaxf(acc0, acc1);
#pragma unroll
    for (int off = 16; off >= 1; off >>= 1)
        m = fmaxf(m, __shfl_xor_sync(0xffffffffu, m, off));
    float s = expf(acc0 - m) + expf(acc1 - m);
#pragma unroll
    for (int off = 16; off >= 1; off >>= 1)
        s += __shfl_xor_sync(0xffffffffu, s, off);
    float lse = m + logf(s);

    out[(size_t)node * OUT_CH + lane]      = acc0 - lse;
    out[(size_t)node * OUT_CH + lane + 32] = acc1 - lse;
}

// ---------------------------------------------------------------- launch
extern "C" void kernel_launch(void* const* d_in, const int* in_sizes, int n_in,
                              void* d_out, int out_size) {
    const float* x   = (const float*)d_in[0];
    const int*   ei1 = (const int*)  d_in[1];
    const float* ew1 = (const float*)d_in[2];
    const int*   ei2 = (const int*)  d_in[3];
    const float* ew2 = (const float*)d_in[4];
    const float* W1  = (const float*)d_in[5];
    const float* b1  = (const float*)d_in[6];
    const float* W2  = (const float*)d_in[7];
    const float* b2  = (const float*)d_in[8];
    float* out = (float*)d_out;

    int n  = in_sizes[0] / IN_CH;
    int E1 = in_sizes[2];
    int E2 = in_sizes[4];
    int Et = E1 + E2;

    const int G1_SMEM = G1_SMEM_FLOATS * (int)sizeof(float);
    cudaFuncSetAttribute(gemm1_kernel, cudaFuncAttributeMaxDynamicSharedMemorySize, G1_SMEM);

    zero_kernel<<<(n * HID / 8 + 255) / 256, 256>>>(n);
    deg_kernel<<<(Et + 255) / 256, 256>>>(ei1, ew1, E1, ei2, ew2, E2);
    dinv_kernel<<<(n + 255) / 256, 256>>>(n);
    gemm1_kernel<<<(n + G1_THREADS - 1) / G1_THREADS, G1_THREADS, G1_SMEM>>>(x, W1, n);
    scatter_kernel<1><<<(2 * Et + 255) / 256, 256>>>(ei1, ew1, E1, ei2, ew2, E2);
    relu_kernel<<<(2 * n + 255) / 256, 256>>>(b1, n);
    scatter_kernel<2><<<(2 * Et + 255) / 256, 256>>>(ei1, ew1, E1, ei2, ew2, E2);
    out_kernel<<<(n + OUT_WARPS - 1) / OUT_WARPS, OUT_WARPS * 32>>>(W2, b2, out, n);
}

// round 13
// speedup vs baseline: 1.2650x; 1.0803x over previous
#include <cuda_runtime.h>
#include <cuda_fp16.h>
#include <cstdint>

#define IN_CH  512
#define HID    16
#define OUT_CH 64
#define MAX_NODES 100352
#define MAX_EDGES 3276800

// ---- scratch (device globals; no allocation allowed) ----
__device__ float  g_deg  [MAX_NODES];
__device__ float  g_dinv [MAX_NODES];
__device__ __half g_h1h  [MAX_NODES * HID];  // fp16 dinv-prescaled x@W1 (3.2MB, L2-resident)
__device__ __half g_zh   [MAX_NODES * HID];  // fp16 dinv*relu(dinv*agg1+b1)
__device__ __half g_agg1h[MAX_NODES * HID];  // fp16 accumulation buffers
__device__ __half g_agg2h[MAX_NODES * HID];

// 128-bit fp16x2 reduction: 8 halves in ONE red-lane-op (the scatter currency)
__device__ __forceinline__ void red_add_v4h2(__half* p, uint32_t r0, uint32_t r1,
                                             uint32_t r2, uint32_t r3) {
    asm volatile("red.global.add.noftz.v4.f16x2 [%0], {%1,%2,%3,%4};"
                 :: "l"(p), "r"(r0), "r"(r1), "r"(r2), "r"(r3) : "memory");
}

__device__ __forceinline__ void cp_async16(uint32_t dst, const void* src) {
    asm volatile("cp.async.cg.shared.global [%0], [%1], 16;" :: "r"(dst), "l"(src));
}

__device__ __forceinline__ uint32_t f2tf32(float f) {
    uint32_t r;
    asm("cvt.rna.tf32.f32 %0, %1;" : "=r"(r) : "f"(f));
    return r;
}

// D += A(16x8) * B(8x8), tf32 inputs, fp32 accum
__device__ __forceinline__ void mma_tf32(float* c, uint32_t a0, uint32_t a1,
                                         uint32_t a2, uint32_t a3,
                                         uint32_t b0, uint32_t b1) {
    asm volatile("mma.sync.aligned.m16n8k8.row.col.f32.tf32.tf32.f32 "
                 "{%0,%1,%2,%3}, {%4,%5,%6,%7}, {%8,%9}, {%0,%1,%2,%3};"
                 : "+f"(c[0]), "+f"(c[1]), "+f"(c[2]), "+f"(c[3])
                 : "r"(a0), "r"(a1), "r"(a2), "r"(a3), "r"(b0), "r"(b1));
}

// ---------------------------------------------------------------- zero (agg1h + deg)
__global__ void zero_kernel(int n) {
    int i = blockIdx.x * blockDim.x + threadIdx.x;
    int t4 = n * HID / 8;            // uint4 = 8 halves
    if (i < t4) ((uint4*)g_agg1h)[i] = make_uint4(0u, 0u, 0u, 0u);
    if (i < n) g_deg[i] = 0.f;
}

// ---------------------------------------------------------------- degree
__global__ void deg_kernel(const int* __restrict__ ei1, const float* __restrict__ w1, int E1,
                           const int* __restrict__ ei2, const float* __restrict__ w2, int E2) {
    int i = blockIdx.x * blockDim.x + threadIdx.x;
    if (i < E1) {
        atomicAdd(&g_deg[ei1[i]], w1[i]);
    } else {
        int j = i - E1;
        if (j < E2) atomicAdd(&g_deg[ei2[j]], w2[j]);
    }
}

__global__ void dinv_kernel(int n) {
    int i = blockIdx.x * blockDim.x + threadIdx.x;
    if (i >= n) return;
    float d = g_deg[i];
    g_dinv[i] = d > 0.f ? rsqrtf(fmaxf(d, 1e-12f)) : 0.f;
}

// ---------------------------------------------------------------- h1h = fp16(dinv .* (x @ W1))  [tf32 tensor cores]
// warp = 16 nodes, 2 mma n-tiles (cols 0-7, 8-15), K=512 in 64 k8-steps.
// W1 pre-packed in smem in exact B-fragment order (float2/lane, LDS.64
// conflict-free). x tile (16 rows x 32 floats/chunk) cp.async double-buffered
// with XOR swizzle conflict-free for STS.128 staging and scalar A-frag LDS.
#define GM_THREADS 256
#define GM_WARPS   8
#define GM_NPW     16
#define GM_TILE    (GM_WARPS * GM_NPW)      // 128 nodes per block
#define GM_KC      32                       // floats per chunk
#define GM_NCHUNK  (IN_CH / GM_KC)          // 16
#define GM_BUF     (GM_NPW * GM_KC)         // 512 floats per buffer (2048 bytes)
#define GM_WF_FLOATS (64 * 2 * 32 * 2)      // 8192 floats = 32KB
#define GM_SMEM_FLOATS (GM_WF_FLOATS + GM_WARPS * 2 * GM_BUF)  // 64KB

__global__ void __launch_bounds__(GM_THREADS, 3)
gemm1_kernel(const float* __restrict__ x, const float* __restrict__ W1, int n) {
    extern __shared__ float smem[];
    float2* Wf = (float2*)smem;             // [ks(64)][tile(2)][lane(32)] -> (b0,b1)
    const int warp = threadIdx.x >> 5;
    const int lane = threadIdx.x & 31;
    float* xb = smem + GM_WF_FLOATS + warp * (2 * GM_BUF);
    const uint32_t xb_s = (uint32_t)__cvta_generic_to_shared(xb);

    // pack W1 into tf32 B fragments: b0 = B[k, n], b1 = B[k+4, n]
    for (int i = threadIdx.x; i < 64 * 2 * 32; i += GM_THREADS) {
        int li = i & 31, tile = (i >> 5) & 1, ks = i >> 6;
        int k = ks * 8 + (li & 3);
        int ncol = tile * 8 + (li >> 2);
        uint32_t b0 = f2tf32(__ldg(W1 + k * HID + ncol));
        uint32_t b1 = f2tf32(__ldg(W1 + (k + 4) * HID + ncol));
        Wf[i] = make_float2(__uint_as_float(b0), __uint_as_float(b1));
    }
    __syncthreads();

    const int nodebase = blockIdx.x * GM_TILE + warp * GM_NPW;
    const int row0 = lane >> 2, row1 = row0 + 8;
    const int k0 = lane & 3;

    // staging: 128 float4 per chunk (16 rows x 8 slots), 4 per lane
    uint32_t st_dst[4];
    const float4* st_src[4];
#pragma unroll
    for (int t = 0; t < 4; t++) {
        int idx = t * 32 + lane;            // 0..127
        int r = idx >> 3, c4 = idx & 7;
        st_dst[t] = xb_s + 16u * (r * 8 + (c4 ^ (r & 7)));
        int nd = nodebase + r;
        st_src[t] = (const float4*)x + ((nd < n) ? (size_t)nd * (IN_CH / 4) : 0) + c4;
    }

    float acc[8];                            // tile0: 0-3, tile1: 4-7
#pragma unroll
    for (int j = 0; j < 8; j++) acc[j] = 0.f;

    // prefetch chunk 0 into buffer 0
#pragma unroll
    for (int t = 0; t < 4; t++) cp_async16(st_dst[t], st_src[t]);
    asm volatile("cp.async.commit_group;" ::: "memory");

    // A-frag smem float offsets (swizzled), constant across chunks except ks
    const int aoff0 = row0 * GM_KC;          // row0*8 slots * 4 floats
    const int aoff1 = row1 * GM_KC;
    const int rs0 = row0 & 7;                // == row1 & 7

    for (int c = 0; c < GM_NCHUNK; c++) {
        if (c + 1 < GM_NCHUNK) {
            const uint32_t nb_off = ((c + 1) & 1) * (GM_BUF * 4u);   // bytes: 0 or 2048
#pragma unroll
            for (int t = 0; t < 4; t++)
                cp_async16(st_dst[t] + nb_off, st_src[t] + (c + 1) * (GM_KC / 4));
            asm volatile("cp.async.commit_group;" ::: "memory");
            asm volatile("cp.async.wait_group 1;" ::: "memory");
        } else {
            asm volatile("cp.async.wait_group 0;" ::: "memory");
        }
        __syncwarp();

        const float* xc = xb + (c & 1) * GM_BUF;
#pragma unroll
        for (int ks = 0; ks < 4; ks++) {
            const int c4a = 2 * ks, c4b = 2 * ks + 1;
            // A fragment: a0=(row0,k), a1=(row1,k), a2=(row0,k+4), a3=(row1,k+4)
            uint32_t a0 = f2tf32(xc[aoff0 + ((c4a ^ rs0) << 2) + k0]);
            uint32_t a1 = f2tf32(xc[aoff1 + ((c4a ^ rs0) << 2) + k0]);
            uint32_t a2 = f2tf32(xc[aoff0 + ((c4b ^ rs0) << 2) + k0]);
            uint32_t a3 = f2tf32(xc[aoff1 + ((c4b ^ rs0) << 2) + k0]);
            const int ksg = c * 4 + ks;
            float2 bA = Wf[(ksg * 2 + 0) * 32 + lane];
            float2 bB = Wf[(ksg * 2 + 1) * 32 + lane];
            mma_tf32(acc,     a0, a1, a2, a3,
                     __float_as_uint(bA.x), __float_as_uint(bA.y));
            mma_tf32(acc + 4, a0, a1, a2, a3,
                     __float_as_uint(bB.x), __float_as_uint(bB.y));
        }
        __syncwarp();
    }

    // epilogue: C layout c0=(row, 2k0), c1=(row, 2k0+1), c2=(row+8, 2k0), c3=(row+8, 2k0+1)
    const int node0 = nodebase + row0;
    const int node1 = nodebase + row1;
    if (node0 < n) {
        float dv = __ldg(g_dinv + node0);
        __half2 t0 = __floats2half2_rn(acc[0] * dv, acc[1] * dv);
        __half2 t1 = __floats2half2_rn(acc[4] * dv, acc[5] * dv);
        *(uint32_t*)(g_h1h + (size_t)node0 * HID + 2 * k0)     = *(uint32_t*)&t0;
        *(uint32_t*)(g_h1h + (size_t)node0 * HID + 8 + 2 * k0) = *(uint32_t*)&t1;
    }
    if (node1 < n) {
        float dv = __ldg(g_dinv + node1);
        __half2 t0 = __floats2half2_rn(acc[2] * dv, acc[3] * dv);
        __half2 t1 = __floats2half2_rn(acc[6] * dv, acc[7] * dv);
        *(uint32_t*)(g_h1h + (size_t)node1 * HID + 2 * k0)     = *(uint32_t*)&t0;
        *(uint32_t*)(g_h1h + (size_t)node1 * HID + 8 + 2 * k0) = *(uint32_t*)&t1;
    }
}

// ---------------------------------------------------------------- scatter (fp16 reds)
// 2 lanes per edge, each: gather 16B (8 halves), scale by w (half2), ONE
// red.v4.f16x2 (8 halves, 128-bit) -> 6.4M red-lane-ops vs 12.8M for fp32.
template <int LAYER>
__global__ void scatter_kernel(const int* __restrict__ ei1, const float* __restrict__ w1, int E1,
                               const int* __restrict__ ei2, const float* __restrict__ w2, int E2) {
    int t = blockIdx.x * blockDim.x + threadIdx.x;
    int e   = t >> 1;
    int sub = t & 1;
    int row, col;
    float w;
    if (e < E1) {
        row = __ldg(ei1 + e); col = __ldg(ei1 + E1 + e); w = __ldg(w1 + e);
    } else {
        int j = e - E1;
        if (j >= E2) return;
        row = __ldg(ei2 + j); col = __ldg(ei2 + E2 + j); w = __ldg(w2 + j);
    }

    const __half* src = (LAYER == 1) ? g_h1h : g_zh;
    __half*       dst = (LAYER == 1) ? g_agg1h : g_agg2h;

    uint4 hv = __ldg((const uint4*)(src + (size_t)col * HID + sub * 8));
    __half2 w2h = __float2half2_rn(w);
    __half2 h0 = __hmul2(*(__half2*)&hv.x, w2h);
    __half2 h1 = __hmul2(*(__half2*)&hv.y, w2h);
    __half2 h2 = __hmul2(*(__half2*)&hv.z, w2h);
    __half2 h3 = __hmul2(*(__half2*)&hv.w, w2h);

    red_add_v4h2(dst + (size_t)row * HID + sub * 8,
                 *(uint32_t*)&h0, *(uint32_t*)&h1, *(uint32_t*)&h2, *(uint32_t*)&h3);
}

// ---------------------------------------------------------------- zh = fp16(dinv.*relu(dinv.*agg1h + b1)); zero agg2h
__global__ void relu_kernel(const float* __restrict__ b1, int n) {
    int i = blockIdx.x * blockDim.x + threadIdx.x;
    if (i >= 2 * n) return;
    int node = i >> 1, sub = i & 1;
    float dv = __ldg(g_dinv + node);
    uint4 u = ((const uint4*)(g_agg1h))[i];
    const float4* bb = (const float4*)(b1 + sub * 8);
    float4 b0 = __ldg(bb), b1v = __ldg(bb + 1);
    float2 f0 = __half22float2(*(__half2*)&u.x);
    float2 f1 = __half22float2(*(__half2*)&u.y);
    float2 f2 = __half22float2(*(__half2*)&u.z);
    float2 f3 = __half22float2(*(__half2*)&u.w);
    f0.x = dv * fmaxf(dv * f0.x + b0.x, 0.f);  f0.y = dv * fmaxf(dv * f0.y + b0.y, 0.f);
    f1.x = dv * fmaxf(dv * f1.x + b0.z, 0.f);  f1.y = dv * fmaxf(dv * f1.y + b0.w, 0.f);
    f2.x = dv * fmaxf(dv * f2.x + b1v.x, 0.f); f2.y = dv * fmaxf(dv * f2.y + b1v.y, 0.f);
    f3.x = dv * fmaxf(dv * f3.x + b1v.z, 0.f); f3.y = dv * fmaxf(dv * f3.y + b1v.w, 0.f);
    __half2 h0 = __floats2half2_rn(f0.x, f0.y);
    __half2 h1 = __floats2half2_rn(f1.x, f1.y);
    __half2 h2 = __floats2half2_rn(f2.x, f2.y);
    __half2 h3 = __floats2half2_rn(f3.x, f3.y);
    ((uint4*)g_zh)[i] = make_uint4(*(unsigned*)&h0, *(unsigned*)&h1,
                                   *(unsigned*)&h2, *(unsigned*)&h3);
    ((uint4*)g_agg2h)[i] = make_uint4(0u, 0u, 0u, 0u);
}

// ---------------------------------------------------------------- out = log_softmax((dinv.*agg2h) @ W2 + b2)
#define OUT_WARPS 8
__global__ void out_kernel(const float* __restrict__ W2, const float* __restrict__ b2,
                           float* __restrict__ out, int n) {
    __shared__ float W2s[HID * OUT_CH];
    for (int t = threadIdx.x; t < HID * OUT_CH / 4; t += blockDim.x)
        ((float4*)W2s)[t] = ((const float4*)W2)[t];
    __syncthreads();

    int warp = threadIdx.x >> 5, lane = threadIdx.x & 31;
    int node = blockIdx.x * OUT_WARPS + warp;
    if (node >= n) return;

    float dv = __ldg(g_dinv + node);
    const uint4* a4 = (const uint4*)(g_agg2h + (size_t)node * HID);
    uint4 u0 = __ldg(a4), u1 = __ldg(a4 + 1);
    float a[16];
    {
        float2 f;
        f = __half22float2(*(__half2*)&u0.x); a[0]  = f.x; a[1]  = f.y;
        f = __half22float2(*(__half2*)&u0.y); a[2]  = f.x; a[3]  = f.y;
        f = __half22float2(*(__half2*)&u0.z); a[4]  = f.x; a[5]  = f.y;
        f = __half22float2(*(__half2*)&u0.w); a[6]  = f.x; a[7]  = f.y;
        f = __half22float2(*(__half2*)&u1.x); a[8]  = f.x; a[9]  = f.y;
        f = __half22float2(*(__half2*)&u1.y); a[10] = f.x; a[11] = f.y;
        f = __half22float2(*(__half2*)&u1.z); a[12] = f.x; a[13] = f.y;
        f = __half22float2(*(__half2*)&u1.w); a[14] = f.x; a[15] = f.y;
    }
#pragma unroll
    for (int k = 0; k < HID; k++) a[k] *= dv;

    float acc0 = b2[lane];
    float acc1 = b2[lane + 32];
#pragma unroll
    for (int k = 0; k < HID; k++) {
        acc0 += a[k] * W2s[k * OUT_CH + lane];
        acc1 += a[k] * W2s[k * OUT_CH + lane + 32];
    }

    float m = fmaxf(acc0, acc1);
#pragma unroll
    for (int off = 16; off >= 1; off >>= 1)
        m = fmaxf(m, __shfl_xor_sync(0xffffffffu, m, off));
    float s = expf(acc0 - m) + expf(acc1 - m);
#pragma unroll
    for (int off = 16; off >= 1; off >>= 1)
        s += __shfl_xor_sync(0xffffffffu, s, off);
    float lse = m + logf(s);

    out[(size_t)node * OUT_CH + lane]      = acc0 - lse;
    out[(size_t)node * OUT_CH + lane + 32] = acc1 - lse;
}

// ---------------------------------------------------------------- launch
extern "C" void kernel_launch(void* const* d_in, const int* in_sizes, int n_in,
                              void* d_out, int out_size) {
    const float* x   = (const float*)d_in[0];
    const int*   ei1 = (const int*)  d_in[1];
    const float* ew1 = (const float*)d_in[2];
    const int*   ei2 = (const int*)  d_in[3];
    const float* ew2 = (const float*)d_in[4];
    const float* W1  = (const float*)d_in[5];
    const float* b1  = (const float*)d_in[6];
    const float* W2  = (const float*)d_in[7];
    const float* b2  = (const float*)d_in[8];
    float* out = (float*)d_out;

    int n  = in_sizes[0] / IN_CH;
    int E1 = in_sizes[2];
    int E2 = in_sizes[4];
    int Et = E1 + E2;

    const int GM_SMEM = GM_SMEM_FLOATS * (int)sizeof(float);
    cudaFuncSetAttribute(gemm1_kernel, cudaFuncAttributeMaxDynamicSharedMemorySize, GM_SMEM);

    zero_kernel<<<(n * HID / 8 + 255) / 256, 256>>>(n);
    deg_kernel<<<(Et + 255) / 256, 256>>>(ei1, ew1, E1, ei2, ew2, E2);
    dinv_kernel<<<(n + 255) / 256, 256>>>(n);
    gemm1_kernel<<<(n + GM_TILE - 1) / GM_TILE, GM_THREADS, GM_SMEM>>>(x, W1, n);
    scatter_kernel<1><<<(2 * Et + 255) / 256, 256>>>(ei1, ew1, E1, ei2, ew2, E2);
    relu_kernel<<<(2 * n + 255) / 256, 256>>>(b1, n);
    scatter_kernel<2><<<(2 * Et + 255) / 256, 256>>>(ei1, ew1, E1, ei2, ew2, E2);
    out_kernel<<<(n + OUT_WARPS - 1) / OUT_WARPS, OUT_WARPS * 32>>>(W2, b2, out, n);
}